// round 3
// baseline (speedup 1.0000x reference)
#include <cuda_runtime.h>
#include <cuda_bf16.h>

// Problem constants
#define BB 32
#define NN 577
#define CC 768
#define C3 (3*CC)

// Scratch (device globals: no allocations allowed)
__device__ float g_qkv[(size_t)BB * NN * C3];   // [B*N, 3C] row-major (q|k|v columns)
__device__ float g_s  [(size_t)BB * NN * NN];   // attention logits / probs
__device__ float g_y  [(size_t)BB * NN * CC];   // attn @ v
__device__ float g_yp [(size_t)BB * NN * CC];   // permuted y (per-b [C,N] flattened)

// ---------------------------------------------------------------------------
// Generic tiled SGEMM:  C = alpha * A @ op(B) (+ bias)
//   A: [M,K] row-major, leading dim lda
//   BT=true : B is [N,K] row-major (computes A @ B^T), leading dim ldb
//   BT=false: B is [K,N] row-major (computes A @ B),  leading dim ldb
//   batched over blockIdx.z with element strides batchA/B/C
// ---------------------------------------------------------------------------
#define BM 128
#define BN 128
#define BK 8
#define TM 8
#define TN 8

template<bool BT>
__global__ __launch_bounds__(256)
void sgemm_kernel(const float* __restrict__ A, const float* __restrict__ B,
                  float* __restrict__ C,
                  int M, int N, int K,
                  int lda, int ldb, int ldc,
                  long long batchA, long long batchB, long long batchC,
                  float alpha, const float* __restrict__ bias)
{
    __shared__ float As[BK][BM];
    __shared__ float Bs[BK][BN];

    const int bz = blockIdx.z;
    A += (long long)bz * batchA;
    B += (long long)bz * batchB;
    C += (long long)bz * batchC;

    const int tid = threadIdx.x;
    const int tx = tid % 16;          // column group
    const int ty = tid / 16;          // row group
    const int row0 = blockIdx.y * BM;
    const int col0 = blockIdx.x * BN;

    float acc[TM][TN];
#pragma unroll
    for (int i = 0; i < TM; i++)
#pragma unroll
        for (int j = 0; j < TN; j++) acc[i][j] = 0.f;

    for (int k0 = 0; k0 < K; k0 += BK) {
        // Load A tile (BM x BK) transposed into As[kk][r]
#pragma unroll
        for (int i = tid; i < BM * BK; i += 256) {
            int r = i / BK, kk = i % BK;
            int gr = row0 + r, gk = k0 + kk;
            As[kk][r] = (gr < M && gk < K) ? A[(long long)gr * lda + gk] : 0.f;
        }
        // Load B tile into Bs[kk][c]
        if (BT) {
#pragma unroll
            for (int i = tid; i < BN * BK; i += 256) {
                int c = i / BK, kk = i % BK;
                int gc = col0 + c, gk = k0 + kk;
                Bs[kk][c] = (gc < N && gk < K) ? B[(long long)gc * ldb + gk] : 0.f;
            }
        } else {
#pragma unroll
            for (int i = tid; i < BK * BN; i += 256) {
                int kk = i / BN, c = i % BN;
                int gc = col0 + c, gk = k0 + kk;
                Bs[kk][c] = (gc < N && gk < K) ? B[(long long)gk * ldb + gc] : 0.f;
            }
        }
        __syncthreads();

#pragma unroll
        for (int kk = 0; kk < BK; kk++) {
            float a[TM], b[TN];
#pragma unroll
            for (int i = 0; i < TM; i++) a[i] = As[kk][ty * TM + i];
#pragma unroll
            for (int j = 0; j < TN; j++) b[j] = Bs[kk][tx * TN + j];
#pragma unroll
            for (int i = 0; i < TM; i++)
#pragma unroll
                for (int j = 0; j < TN; j++) acc[i][j] += a[i] * b[j];
        }
        __syncthreads();
    }

#pragma unroll
    for (int i = 0; i < TM; i++) {
        int gr = row0 + ty * TM + i;
        if (gr >= M) continue;
#pragma unroll
        for (int j = 0; j < TN; j++) {
            int gc = col0 + tx * TN + j;
            if (gc >= N) continue;
            float v = alpha * acc[i][j];
            if (bias) v += bias[gc];
            C[(long long)gr * ldc + gc] = v;
        }
    }
}

// ---------------------------------------------------------------------------
// Row softmax over S (in place), length NN per row. Also emits token_attn for
// row 0 of each batch: token_out[b*576 + (m-1)] = attn[b,0,m], m in [1,577).
// ---------------------------------------------------------------------------
__global__ __launch_bounds__(256)
void softmax_kernel(float* __restrict__ S, float* __restrict__ token_out)
{
    const int row = blockIdx.x;
    const int b = blockIdx.y;
    float* srow = S + ((long long)b * NN + row) * NN;

    __shared__ float red[256];
    const int tid = threadIdx.x;

    float m = -1e30f;
    for (int i = tid; i < NN; i += 256) m = fmaxf(m, srow[i]);
    red[tid] = m;
    __syncthreads();
    for (int s = 128; s > 0; s >>= 1) {
        if (tid < s) red[tid] = fmaxf(red[tid], red[tid + s]);
        __syncthreads();
    }
    m = red[0];
    __syncthreads();

    float sum = 0.f;
    for (int i = tid; i < NN; i += 256) {
        float e = __expf(srow[i] - m);
        srow[i] = e;
        sum += e;
    }
    red[tid] = sum;
    __syncthreads();
    for (int s = 128; s > 0; s >>= 1) {
        if (tid < s) red[tid] += red[tid + s];
        __syncthreads();
    }
    const float inv = 1.f / red[0];

    for (int i = tid; i < NN; i += 256) {
        float p = srow[i] * inv;
        srow[i] = p;
        if (row == 0 && i >= 1)
            token_out[(long long)b * (NN - 1) + (i - 1)] = p;
    }
}

// ---------------------------------------------------------------------------
// Per-batch transpose: yp[b, c*NN + n] = y[b, n*CC + c]
// (implements transpose(0,2,1).reshape of the reference)
// ---------------------------------------------------------------------------
__global__ void transpose_kernel(const float* __restrict__ y, float* __restrict__ yp)
{
    __shared__ float t[32][33];
    const int b = blockIdx.z;
    const int c0 = blockIdx.x * 32;
    const int n0 = blockIdx.y * 32;
    const float* yb = y + (long long)b * NN * CC;
    float* ypb = yp + (long long)b * NN * CC;

    const int x = threadIdx.x;
    const int yy = threadIdx.y;

    for (int i = yy; i < 32; i += 8) {
        int n = n0 + i, c = c0 + x;
        if (n < NN && c < CC) t[i][x] = yb[(long long)n * CC + c];
    }
    __syncthreads();
    for (int i = yy; i < 32; i += 8) {
        int c = c0 + i, n = n0 + x;
        if (n < NN && c < CC) ypb[(long long)c * NN + n] = t[x][i];
    }
}

// ---------------------------------------------------------------------------
extern "C" void kernel_launch(void* const* d_in, const int* in_sizes, int n_in,
                              void* d_out, int out_size)
{
    const float* x      = (const float*)d_in[0];  // [32,577,768]
    const float* w_qkv  = (const float*)d_in[1];  // [2304,768]
    const float* w_proj = (const float*)d_in[2];  // [768,768]
    const float* b_proj = (const float*)d_in[3];  // [768]

    float* out = (float*)d_out;                          // [32,577,768]
    float* token_out = out + (size_t)BB * NN * CC;       // [32,576]

    float *qkv, *s, *y, *yp;
    cudaGetSymbolAddress((void**)&qkv, g_qkv);
    cudaGetSymbolAddress((void**)&s,   g_s);
    cudaGetSymbolAddress((void**)&y,   g_y);
    cudaGetSymbolAddress((void**)&yp,  g_yp);

    const int M1 = BB * NN;                 // 18464
    const dim3 blk(256);
    const float scale = 0.03608439182435161f;  // 768^-0.5

    // 1) qkv = x @ w_qkv^T  -> [M1, 2304]
    {
        dim3 grid((C3 + BN - 1) / BN, (M1 + BM - 1) / BM, 1);
        sgemm_kernel<true><<<grid, blk>>>(x, w_qkv, qkv,
                                          M1, C3, CC,
                                          CC, CC, C3,
                                          0, 0, 0, 1.f, nullptr);
    }
    // 2) S[b] = scale * q[b] @ k[b]^T   (q = qkv col 0, k = qkv col 768)
    {
        dim3 grid((NN + BN - 1) / BN, (NN + BM - 1) / BM, BB);
        sgemm_kernel<true><<<grid, blk>>>(qkv, qkv + CC, s,
                                          NN, NN, CC,
                                          C3, C3, NN,
                                          (long long)NN * C3, (long long)NN * C3,
                                          (long long)NN * NN, scale, nullptr);
    }
    // 3) softmax rows (+ token_attn output)
    softmax_kernel<<<dim3(NN, BB), 256>>>(s, token_out);

    // 4) y[b] = P[b] @ v[b]   (v = qkv col 1536, B non-transposed [K,N])
    {
        dim3 grid((CC + BN - 1) / BN, (NN + BM - 1) / BM, BB);
        sgemm_kernel<false><<<grid, blk>>>(s, qkv + 2 * CC, y,
                                           NN, CC, NN,
                                           NN, C3, CC,
                                           (long long)NN * NN, (long long)NN * C3,
                                           (long long)NN * CC, 1.f, nullptr);
    }
    // 5) permute: yp[b] = flatten(transpose(y[b]))
    transpose_kernel<<<dim3(CC / 32, (NN + 31) / 32, BB), dim3(32, 8)>>>(y, yp);

    // 6) out = yp @ w_proj^T + b_proj
    {
        dim3 grid((CC + BN - 1) / BN, (M1 + BM - 1) / BM, 1);
        sgemm_kernel<true><<<grid, blk>>>(yp, w_proj, out,
                                          M1, CC, CC,
                                          CC, CC, CC,
                                          0, 0, 0, 1.f, b_proj);
    }
}

// round 11
// speedup vs baseline: 2.7464x; 2.7464x over previous
#include <cuda_runtime.h>
#include <cuda_bf16.h>
#include <cstdint>

// Problem constants
#define BB 32
#define NN 577
#define CC 768
#define C3 (3*CC)
#define SD 640               // padded leading dim for S and vT (16B-aligned rows)

// Scratch (device globals: no allocations allowed)
__device__ float g_qkv[(size_t)BB * NN * C3];   // [B*N, 3C] (q|k|v)
__device__ float g_s  [(size_t)BB * NN * SD];   // attention logits/probs, ld=640
__device__ float g_y  [(size_t)BB * NN * CC];   // attn @ v
__device__ float g_yp [(size_t)BB * NN * CC];   // permuted y (contiguous per-b [C,N])
__device__ float g_vT [(size_t)BB * CC * SD];   // v transposed, [768,640] per batch

// ---------------------------------------------------------------------------
// Helpers (all plain sm_80-era PTX: compiles for non-'a' sm_103 target)
// ---------------------------------------------------------------------------
__device__ __forceinline__ uint32_t smem_u32(const void* p) {
    uint32_t a;
    asm("{ .reg .u64 t; cvta.to.shared.u64 t, %1; cvt.u32.u64 %0, t; }" : "=r"(a) : "l"(p));
    return a;
}

// split fp32 pair into packed bf16x2 hi and lo (error compensation)
__device__ __forceinline__ void split2(float f0, float f1, uint32_t& hi, uint32_t& lo) {
    uint32_t h;
    asm("cvt.rn.bf16x2.f32 %0, %1, %2;" : "=r"(h) : "f"(f1), "f"(f0));
    float f0h = __uint_as_float(h << 16);
    float f1h = __uint_as_float(h & 0xffff0000u);
    float r0 = f0 - f0h;
    float r1 = f1 - f1h;
    uint32_t l;
    asm("cvt.rn.bf16x2.f32 %0, %1, %2;" : "=r"(l) : "f"(r1), "f"(r0));
    hi = h; lo = l;
}

__device__ __forceinline__ void ldsm4(uint32_t addr, uint32_t* r) {
    asm volatile("ldmatrix.sync.aligned.m8n8.x4.shared.b16 {%0,%1,%2,%3}, [%4];"
        : "=r"(r[0]), "=r"(r[1]), "=r"(r[2]), "=r"(r[3]) : "r"(addr));
}

__device__ __forceinline__ void mma16816(float* d, const uint32_t* a, const uint32_t* b) {
    asm volatile("mma.sync.aligned.m16n8k16.row.col.f32.bf16.bf16.f32 "
        "{%0,%1,%2,%3}, {%4,%5,%6,%7}, {%8,%9}, {%0,%1,%2,%3};"
        : "+f"(d[0]), "+f"(d[1]), "+f"(d[2]), "+f"(d[3])
        : "r"(a[0]), "r"(a[1]), "r"(a[2]), "r"(a[3]), "r"(b[0]), "r"(b[1]));
}

// ---------------------------------------------------------------------------
// mma.sync split-bf16 GEMM:  C = alpha * A @ B^T (+ bias)
//   A: [M,K] row-major lda (16B-aligned rows), B: [N,K] row-major ldb.
//   CTA tile 128x128, K-chunk 32, double-buffered smem, fp32 accum in regs.
//   K must be a multiple of 32.
// ---------------------------------------------------------------------------
#define KC 32
#define RSTRIDE 80                  // smem bytes per 32-bf16 row (64B data + 16B pad)
#define TILEB (128 * RSTRIDE)       // 10240 B per tile
#define STAGEB (4 * TILEB)          // Ahi,Alo,Bhi,Blo
#define SMEM_TOTAL (2 * STAGEB)     // 81920 B

__device__ __forceinline__ void ldg_tile(const float* __restrict__ src, int nrows, int ld,
                                         int row, int kb, float4* v) {
    const float* p = src + (long long)row * ld + kb;
    const bool ok = row < nrows;
#pragma unroll
    for (int j = 0; j < 4; j++)
        v[j] = ok ? *reinterpret_cast<const float4*>(p + 4 * j) : make_float4(0.f, 0.f, 0.f, 0.f);
}

__device__ __forceinline__ void sts_tile(char* smp, uint32_t off_hi, uint32_t off_lo,
                                         int row, int kb, const float4* v) {
#pragma unroll
    for (int j = 0; j < 4; j++) {
        uint32_t h0, l0, h1, l1;
        split2(v[j].x, v[j].y, h0, l0);
        split2(v[j].z, v[j].w, h1, l1);
        uint32_t off = (uint32_t)(row * RSTRIDE + (kb + 4 * j) * 2);
        *reinterpret_cast<uint2*>(smp + off_hi + off) = make_uint2(h0, h1);
        *reinterpret_cast<uint2*>(smp + off_lo + off) = make_uint2(l0, l1);
    }
}

__global__ __launch_bounds__(256, 1)
void mma_gemm(const float* __restrict__ A, const float* __restrict__ B, float* __restrict__ C,
              int M, int N, int K, int lda, int ldb, int ldc,
              long long bA, long long bB, long long bC,
              float alpha, const float* __restrict__ bias)
{
    extern __shared__ __align__(128) char sm[];
    const int tid = threadIdx.x;
    const int wid = tid >> 5;
    const int lane = tid & 31;

    A += (long long)blockIdx.z * bA;
    B += (long long)blockIdx.z * bB;
    C += (long long)blockIdx.z * bC;
    const int row0 = blockIdx.y * 128;
    const int col0 = blockIdx.x * 128;
    const int nrA = min(128, M - row0);
    const int nrB = min(128, N - col0);
    const uint32_t sb = smem_u32(sm);

    // warp tiling: 4 (M) x 2 (N), warp tile 32x64
    const int wm = wid >> 1;
    const int wn = wid & 1;
    // ldmatrix lane byte offsets within a tile
    const uint32_t a_loff = (uint32_t)((wm * 32 + (lane & 15)) * RSTRIDE + (lane >> 4) * 16);
    const uint32_t b_loff = (uint32_t)((wn * 64 + (lane & 7) + ((lane >> 4) & 1) * 8) * RSTRIDE
                                       + ((lane >> 3) & 1) * 16);
    // global staging assignment: thread -> (row, 16-wide k slab)
    const int lrow = tid >> 1;
    const int lkb = (tid & 1) * 16;

    float acc[2][8][4];
#pragma unroll
    for (int mt = 0; mt < 2; mt++)
#pragma unroll
        for (int nt = 0; nt < 8; nt++)
#pragma unroll
            for (int j = 0; j < 4; j++) acc[mt][nt][j] = 0.f;

    const int NC = K / KC;
    const float* Ab = A + (long long)row0 * lda;
    const float* Bb = B + (long long)col0 * ldb;

    float4 va[4], vb[4];
    ldg_tile(Ab, nrA, lda, lrow, lkb, va);
    ldg_tile(Bb, nrB, ldb, lrow, lkb, vb);
    sts_tile(sm, 0 * TILEB, 1 * TILEB, lrow, lkb, va);
    sts_tile(sm, 2 * TILEB, 3 * TILEB, lrow, lkb, vb);
    __syncthreads();

    for (int c = 0; c < NC; c++) {
        if (c + 1 < NC) {
            ldg_tile(Ab + (c + 1) * KC, nrA, lda, lrow, lkb, va);
            ldg_tile(Bb + (c + 1) * KC, nrB, ldb, lrow, lkb, vb);
        }
        const uint32_t stb = sb + (uint32_t)((c & 1) * STAGEB);
#pragma unroll
        for (int ks = 0; ks < 2; ks++) {
            uint32_t ahi[2][4], alo[2][4], bhi[4][4], blo[4][4];
#pragma unroll
            for (int mt = 0; mt < 2; mt++) {
                ldsm4(stb + 0 * TILEB + a_loff + mt * 16 * RSTRIDE + ks * 32, ahi[mt]);
                ldsm4(stb + 1 * TILEB + a_loff + mt * 16 * RSTRIDE + ks * 32, alo[mt]);
            }
#pragma unroll
            for (int p = 0; p < 4; p++) {
                ldsm4(stb + 2 * TILEB + b_loff + p * 16 * RSTRIDE + ks * 32, bhi[p]);
                ldsm4(stb + 3 * TILEB + b_loff + p * 16 * RSTRIDE + ks * 32, blo[p]);
            }
#pragma unroll
            for (int mt = 0; mt < 2; mt++)
#pragma unroll
                for (int nt = 0; nt < 8; nt++) {
                    const uint32_t* bh = &bhi[nt >> 1][(nt & 1) * 2];
                    const uint32_t* bl = &blo[nt >> 1][(nt & 1) * 2];
                    mma16816(acc[mt][nt], ahi[mt], bh);
                    mma16816(acc[mt][nt], ahi[mt], bl);
                    mma16816(acc[mt][nt], alo[mt], bh);
                }
        }
        if (c + 1 < NC) {
            char* nst = sm + ((c + 1) & 1) * STAGEB;
            sts_tile(nst, 0 * TILEB, 1 * TILEB, lrow, lkb, va);
            sts_tile(nst, 2 * TILEB, 3 * TILEB, lrow, lkb, vb);
        }
        __syncthreads();
    }

    // Epilogue: write accumulators
#pragma unroll
    for (int mt = 0; mt < 2; mt++) {
#pragma unroll
        for (int nt = 0; nt < 8; nt++) {
            const int r = row0 + wm * 32 + mt * 16 + (lane >> 2);
            const int cg = col0 + wn * 64 + nt * 8 + (lane & 3) * 2;
#pragma unroll
            for (int h = 0; h < 2; h++) {
                const int rr = r + h * 8;
                if (rr < M) {
                    float v0 = alpha * acc[mt][nt][2 * h + 0];
                    float v1 = alpha * acc[mt][nt][2 * h + 1];
                    if (cg + 1 < N) {
                        if (bias) { v0 += bias[cg]; v1 += bias[cg + 1]; }
                        *reinterpret_cast<float2*>(C + (long long)rr * ldc + cg) = make_float2(v0, v1);
                    } else if (cg < N) {
                        if (bias) v0 += bias[cg];
                        C[(long long)rr * ldc + cg] = v0;
                    }
                }
            }
        }
    }
}

// ---------------------------------------------------------------------------
// Row softmax over S (ld = SD), emits token_attn from row 0 of each batch.
// Also zero-fills pad columns [NN, SD) so PV GEMM can run K = SD.
// ---------------------------------------------------------------------------
__global__ __launch_bounds__(256)
void softmax_kernel(float* __restrict__ S, float* __restrict__ token_out)
{
    const int row = blockIdx.x;
    const int b = blockIdx.y;
    float* srow = S + ((long long)b * NN + row) * SD;

    __shared__ float red[256];
    const int tid = threadIdx.x;

    float m = -1e30f;
    for (int i = tid; i < NN; i += 256) m = fmaxf(m, srow[i]);
    red[tid] = m;
    __syncthreads();
    for (int s = 128; s > 0; s >>= 1) {
        if (tid < s) red[tid] = fmaxf(red[tid], red[tid + s]);
        __syncthreads();
    }
    m = red[0];
    __syncthreads();

    float sum = 0.f;
    for (int i = tid; i < NN; i += 256) {
        float e = __expf(srow[i] - m);
        srow[i] = e;
        sum += e;
    }
    red[tid] = sum;
    __syncthreads();
    for (int s = 128; s > 0; s >>= 1) {
        if (tid < s) red[tid] += red[tid + s];
        __syncthreads();
    }
    const float inv = 1.f / red[0];

    for (int i = tid; i < NN; i += 256) {
        float p = srow[i] * inv;
        srow[i] = p;
        if (row == 0 && i >= 1)
            token_out[(long long)b * (NN - 1) + (i - 1)] = p;
    }
    // zero pad columns so downstream GEMM can use K = SD
    for (int i = NN + tid; i < SD; i += 256) srow[i] = 0.f;
}

// ---------------------------------------------------------------------------
// Generic batched transpose: out[c*ldo + r] = in[r*ldi + c], in is [R, Cc].
// ---------------------------------------------------------------------------
__global__ void transpose_kernel(const float* __restrict__ in, float* __restrict__ out,
                                 int R, int Cc, int ldi, int ldo,
                                 long long bi, long long bo)
{
    __shared__ float t[32][33];
    const int b = blockIdx.z;
    const float* ib = in + (long long)b * bi;
    float* ob = out + (long long)b * bo;
    const int c0 = blockIdx.x * 32;
    const int r0 = blockIdx.y * 32;
    const int x = threadIdx.x;
    const int yy = threadIdx.y;

    for (int i = yy; i < 32; i += 8) {
        int r = r0 + i, c = c0 + x;
        if (r < R && c < Cc) t[i][x] = ib[(long long)r * ldi + c];
    }
    __syncthreads();
    for (int i = yy; i < 32; i += 8) {
        int c = c0 + i, r = r0 + x;
        if (r < R && c < Cc) ob[(long long)c * ldo + r] = t[x][i];
    }
}

// ---------------------------------------------------------------------------
extern "C" void kernel_launch(void* const* d_in, const int* in_sizes, int n_in,
                              void* d_out, int out_size)
{
    const float* x      = (const float*)d_in[0];  // [32,577,768]
    const float* w_qkv  = (const float*)d_in[1];  // [2304,768]
    const float* w_proj = (const float*)d_in[2];  // [768,768]
    const float* b_proj = (const float*)d_in[3];  // [768]

    float* out = (float*)d_out;                          // [32,577,768]
    float* token_out = out + (size_t)BB * NN * CC;       // [32,576]

    float *qkv, *s, *y, *yp, *vT;
    cudaGetSymbolAddress((void**)&qkv, g_qkv);
    cudaGetSymbolAddress((void**)&s,   g_s);
    cudaGetSymbolAddress((void**)&y,   g_y);
    cudaGetSymbolAddress((void**)&yp,  g_yp);
    cudaGetSymbolAddress((void**)&vT,  g_vT);

    cudaFuncSetAttribute(mma_gemm, cudaFuncAttributeMaxDynamicSharedMemorySize, SMEM_TOTAL);

    const int M1 = BB * NN;                    // 18464
    const float scale = 0.03608439182435161f;  // 768^-0.5
    const dim3 blk(256);

    // 1) qkv = x @ w_qkv^T  [18464, 2304], K=768
    mma_gemm<<<dim3(C3 / 128, (M1 + 127) / 128, 1), blk, SMEM_TOTAL>>>(
        x, w_qkv, qkv, M1, C3, CC, CC, CC, C3, 0, 0, 0, 1.f, nullptr);

    // 1b) vT[b] = v[b]^T  (v rows at qkv col 1536) -> [768 x 640-padded]
    //     (pad cols of vT stay zero from static init; pads of S are zeroed in softmax)
    transpose_kernel<<<dim3(CC / 32, (NN + 31) / 32, BB), dim3(32, 8)>>>(
        qkv + 2 * CC, vT, NN, CC, C3, SD,
        (long long)NN * C3, (long long)CC * SD);

    // 2) S[b] = scale * q[b] @ k[b]^T  [577,577], ld=640, K=768
    mma_gemm<<<dim3((NN + 127) / 128, (NN + 127) / 128, BB), blk, SMEM_TOTAL>>>(
        qkv, qkv + CC, s, NN, NN, CC, C3, C3, SD,
        (long long)NN * C3, (long long)NN * C3, (long long)NN * SD, scale, nullptr);

    // 3) softmax rows (+ token_attn, + zero pads)
    softmax_kernel<<<dim3(NN, BB), 256>>>(s, token_out);

    // 4) y[b] = P[b] @ (vT[b])^T  [577,768], K=640 (zero-padded)
    mma_gemm<<<dim3(CC / 128, (NN + 127) / 128, BB), blk, SMEM_TOTAL>>>(
        s, vT, y, NN, CC, SD, SD, SD, CC,
        (long long)NN * SD, (long long)CC * SD, (long long)NN * CC, 1.f, nullptr);

    // 5) yp[b] = flatten(y[b]^T)  (contiguous [C,N] per batch)
    transpose_kernel<<<dim3(CC / 32, (NN + 31) / 32, BB), dim3(32, 8)>>>(
        y, yp, NN, CC, CC, NN,
        (long long)NN * CC, (long long)NN * CC);

    // 6) out = yp @ w_proj^T + b_proj  [18464, 768], K=768
    mma_gemm<<<dim3(CC / 128, (M1 + 127) / 128, 1), blk, SMEM_TOTAL>>>(
        yp, w_proj, out, M1, CC, CC, CC, CC, CC, 0, 0, 0, 1.f, b_proj);
}